// round 1
// baseline (speedup 1.0000x reference)
#include <cuda_runtime.h>
#include <cstdint>
#include <cstddef>

// Problem constants
#define BATCH 64
#define CH    512            // WIDTH == C_IN == 512
#define LSEQ  512
#define MAT   (CH * LSEQ)          // 262144 elems per [512,512] matrix
#define NMAT  (BATCH * MAT)        // 16777216 elems per [64,512,512] tensor

// ---------------- scratch (device globals; no allocation allowed) ------------
__device__ float g_Y[3ULL * NMAT];     // Q,K,V post-projection (192 MB)
__device__ float g_Wscore[NMAT];       // attention scores / weights (64 MB)
__device__ float g_X[2ULL * NMAT];     // ping-pong activations (128 MB)
__device__ float g_sum[3 * CH];
__device__ float g_sq[3 * CH];
__device__ float g_mean[3 * CH];
__device__ float g_rstd[3 * CH];

// ---------------- GEMM: C[b] = A (opt batched) * op(B[b]) -------------------
// M=N=K=512 fixed. Tile 128x128x16, 256 threads, 8x8 per thread.
// TRANSB=false: B is [K][N] row-major (projection: X[b], out: V[b])
// TRANSB=true : B is [N][K] row-major (attention: K[b], dot over L)
// STATS=true  : add bias[row], accumulate per-row sum / sumsq via atomics.
#define TK 16
#define ASLD 132

template<bool TRANSB, bool STATS>
__launch_bounds__(256)
__global__ void gemm512(const float* __restrict__ A, int batchedA,
                        const float* __restrict__ Bm,
                        float* __restrict__ C,
                        const float* __restrict__ bias,
                        float* __restrict__ sums,
                        float* __restrict__ sqs)
{
    constexpr int BSLD = TRANSB ? 132 : 128;
    __shared__ float As[2][TK][ASLD];
    __shared__ float Bs[2][TK][BSLD];

    const int tid = threadIdx.x;
    const int tx  = tid & 15;
    const int ty  = tid >> 4;
    const int m0  = blockIdx.y * 128;
    const int n0  = blockIdx.x * 128;
    const int b   = blockIdx.z;

    const float* Ab = A  + (batchedA ? (size_t)b * MAT : 0);
    const float* Bb = Bm + (size_t)b * MAT;
    float*       Cb = C  + (size_t)b * MAT;

    // A loader: 128 rows x 16 k, row-major [M][K]; store transposed to As[k][m]
    const int la_r = tid >> 2;          // 0..63 (+64 on 2nd pass)
    const int la_c = (tid & 3) * 4;     // 0,4,8,12
    const float* Ap = Ab + (size_t)(m0 + la_r) * CH + la_c;

    // B loader
    const float* Bp = nullptr;
    int lb_r = 0, lb_c = 0;
    if (TRANSB) {
        Bp = Bb + (size_t)(n0 + la_r) * CH + la_c;          // [N][K] rows
    } else {
        lb_r = tid >> 5;                                    // 0..7 (+8)
        lb_c = (tid & 31) * 4;                              // 0..124
        Bp = Bb + (size_t)lb_r * LSEQ + n0 + lb_c;          // [K][N] rows
    }

    float4 aR0, aR1, bR0, bR1;

    auto ldg = [&](int kt) {
        aR0 = *(const float4*)(Ap + kt * TK);
        aR1 = *(const float4*)(Ap + 64 * CH + kt * TK);
        if (TRANSB) {
            bR0 = *(const float4*)(Bp + kt * TK);
            bR1 = *(const float4*)(Bp + 64 * CH + kt * TK);
        } else {
            bR0 = *(const float4*)(Bp + (size_t)kt * TK * LSEQ);
            bR1 = *(const float4*)(Bp + (size_t)kt * TK * LSEQ + 8 * LSEQ);
        }
    };
    auto sts = [&](int buf) {
        As[buf][la_c + 0][la_r]      = aR0.x;
        As[buf][la_c + 1][la_r]      = aR0.y;
        As[buf][la_c + 2][la_r]      = aR0.z;
        As[buf][la_c + 3][la_r]      = aR0.w;
        As[buf][la_c + 0][la_r + 64] = aR1.x;
        As[buf][la_c + 1][la_r + 64] = aR1.y;
        As[buf][la_c + 2][la_r + 64] = aR1.z;
        As[buf][la_c + 3][la_r + 64] = aR1.w;
        if (TRANSB) {
            Bs[buf][la_c + 0][la_r]      = bR0.x;
            Bs[buf][la_c + 1][la_r]      = bR0.y;
            Bs[buf][la_c + 2][la_r]      = bR0.z;
            Bs[buf][la_c + 3][la_r]      = bR0.w;
            Bs[buf][la_c + 0][la_r + 64] = bR1.x;
            Bs[buf][la_c + 1][la_r + 64] = bR1.y;
            Bs[buf][la_c + 2][la_r + 64] = bR1.z;
            Bs[buf][la_c + 3][la_r + 64] = bR1.w;
        } else {
            *(float4*)&Bs[buf][lb_r][lb_c]     = bR0;
            *(float4*)&Bs[buf][lb_r + 8][lb_c] = bR1;
        }
    };

    float acc[8][8];
#pragma unroll
    for (int i = 0; i < 8; i++)
#pragma unroll
        for (int j = 0; j < 8; j++) acc[i][j] = 0.f;

    ldg(0);
    sts(0);
    __syncthreads();

    for (int kt = 0; kt < 32; ++kt) {
        const int cur = kt & 1;
        if (kt < 31) ldg(kt + 1);
#pragma unroll
        for (int k = 0; k < TK; ++k) {
            float af[8], bf[8];
            *(float4*)(af)     = *(const float4*)&As[cur][k][ty * 8];
            *(float4*)(af + 4) = *(const float4*)&As[cur][k][ty * 8 + 4];
            *(float4*)(bf)     = *(const float4*)&Bs[cur][k][tx * 8];
            *(float4*)(bf + 4) = *(const float4*)&Bs[cur][k][tx * 8 + 4];
#pragma unroll
            for (int i = 0; i < 8; i++)
#pragma unroll
                for (int j = 0; j < 8; j++)
                    acc[i][j] = fmaf(af[i], bf[j], acc[i][j]);
        }
        if (kt < 31) sts(cur ^ 1);
        __syncthreads();
    }

    // epilogue
#pragma unroll
    for (int i = 0; i < 8; i++) {
        const int row = m0 + ty * 8 + i;
        if (STATS) {
            const float bv = bias[row];
#pragma unroll
            for (int j = 0; j < 8; j++) acc[i][j] += bv;
        }
        float4 v0 = make_float4(acc[i][0], acc[i][1], acc[i][2], acc[i][3]);
        float4 v1 = make_float4(acc[i][4], acc[i][5], acc[i][6], acc[i][7]);
        *(float4*)&Cb[(size_t)row * LSEQ + n0 + tx * 8]     = v0;
        *(float4*)&Cb[(size_t)row * LSEQ + n0 + tx * 8 + 4] = v1;
        if (STATS) {
            float s = 0.f, q = 0.f;
#pragma unroll
            for (int j = 0; j < 8; j++) { s += acc[i][j]; q += acc[i][j] * acc[i][j]; }
#pragma unroll
            for (int off = 8; off > 0; off >>= 1) {
                s += __shfl_xor_sync(0xffffffffu, s, off);
                q += __shfl_xor_sync(0xffffffffu, q, off);
            }
            if (tx == 0) {
                atomicAdd(&sums[row], s);
                atomicAdd(&sqs[row], q);
            }
        }
    }
}

// ---------------- small kernels ----------------------------------------------
__global__ void zero_stats()
{
    int i = blockIdx.x * blockDim.x + threadIdx.x;
    if (i < 3 * CH) { g_sum[i] = 0.f; g_sq[i] = 0.f; }
}

__global__ void finalize_stats()
{
    int i = blockIdx.x * blockDim.x + threadIdx.x;
    if (i < 3 * CH) {
        const float inv_n = 1.0f / (float)(BATCH * LSEQ);
        float m = g_sum[i] * inv_n;
        float v = g_sq[i] * inv_n - m * m;
        g_mean[i] = m;
        g_rstd[i] = rsqrtf(v + 1e-5f);
    }
}

__global__ void bn_relu(float* __restrict__ Y, const float* __restrict__ gamma,
                        const float* __restrict__ beta, int statOff)
{
    size_t i = (size_t)blockIdx.x * blockDim.x + threadIdx.x;  // over NMAT/4
    float4* p = (float4*)Y;
    const int c = (int)((i >> 7) & 511);                       // channel (512 f = 128 f4 per row)
    const float m  = g_mean[statOff + c];
    const float r  = g_rstd[statOff + c];
    const float sc = r * gamma[c];
    const float sh = beta[c] - m * sc;
    float4 v = p[i];
    v.x = fmaxf(fmaf(v.x, sc, sh), 0.f);
    v.y = fmaxf(fmaf(v.y, sc, sh), 0.f);
    v.z = fmaxf(fmaf(v.z, sc, sh), 0.f);
    v.w = fmaxf(fmaf(v.w, sc, sh), 0.f);
    p[i] = v;
}

// softmax over the BATCH axis (dim 0): 64 values per (c,d), kept in registers
__global__ void softmax_batch(float* __restrict__ W)
{
    const int cd = blockIdx.x * blockDim.x + threadIdx.x;  // 0..262143
    float v[BATCH];
    float mx = -3.402823e38f;
#pragma unroll
    for (int b = 0; b < BATCH; b++) {
        v[b] = W[(size_t)b * MAT + cd];
        mx = fmaxf(mx, v[b]);
    }
    float s = 0.f;
#pragma unroll
    for (int b = 0; b < BATCH; b++) { v[b] = expf(v[b] - mx); s += v[b]; }
    const float r = 1.0f / s;
#pragma unroll
    for (int b = 0; b < BATCH; b++) W[(size_t)b * MAT + cd] = v[b] * r;
}

// ---------------- orchestration ----------------------------------------------
extern "C" void kernel_launch(void* const* d_in, const int* /*in_sizes*/, int /*n_in*/,
                              void* d_out, int /*out_size*/)
{
    const float* P     = (const float*)d_in[0];
    const float* Wq    = (const float*)d_in[1];
    const float* bq    = (const float*)d_in[2];
    const float* gq    = (const float*)d_in[3];
    const float* betaq = (const float*)d_in[4];
    const float* Wk    = (const float*)d_in[5];
    const float* bk    = (const float*)d_in[6];
    const float* gk    = (const float*)d_in[7];
    const float* betak = (const float*)d_in[8];
    const float* Wv    = (const float*)d_in[9];
    const float* bv    = (const float*)d_in[10];
    const float* gv    = (const float*)d_in[11];
    const float* betav = (const float*)d_in[12];

    float *Y, *Wsc, *X, *sum, *sq;
    cudaGetSymbolAddress((void**)&Y,   g_Y);
    cudaGetSymbolAddress((void**)&Wsc, g_Wscore);
    cudaGetSymbolAddress((void**)&X,   g_X);
    cudaGetSymbolAddress((void**)&sum, g_sum);
    cudaGetSymbolAddress((void**)&sq,  g_sq);

    const dim3 gg(4, 4, BATCH);

    for (int d = 0; d < 3; d++) {
        const float* xin  = (d == 0) ? P : X + (size_t)(d - 1) * NMAT;
        float*       xout = (d == 2) ? (float*)d_out : X + (size_t)d * NMAT;

        const float* Ws[3] = {Wq + (size_t)d * MAT, Wk + (size_t)d * MAT, Wv + (size_t)d * MAT};
        const float* bs[3] = {bq + d * CH, bk + d * CH, bv + d * CH};
        const float* gs[3] = {gq + d * CH, gk + d * CH, gv + d * CH};
        const float* be[3] = {betaq + d * CH, betak + d * CH, betav + d * CH};

        zero_stats<<<6, 256>>>();

        for (int p = 0; p < 3; p++)
            gemm512<false, true><<<gg, 256>>>(Ws[p], 0, xin, Y + (size_t)p * NMAT,
                                              bs[p], sum + p * CH, sq + p * CH);

        finalize_stats<<<6, 256>>>();

        for (int p = 0; p < 3; p++)
            bn_relu<<<NMAT / 4 / 256, 256>>>(Y + (size_t)p * NMAT, gs[p], be[p], p * CH);

        // scores: w[b] = Q[b] * K[b]^T   (dot over L)
        gemm512<true, false><<<gg, 256>>>(Y, 1, Y + (size_t)1 * NMAT, Wsc,
                                          nullptr, nullptr, nullptr);

        softmax_batch<<<MAT / 256, 256>>>(Wsc);

        // x = a[b] * V[b]
        gemm512<false, false><<<gg, 256>>>(Wsc, 1, Y + (size_t)2 * NMAT, xout,
                                           nullptr, nullptr, nullptr);
    }
}

// round 3
// speedup vs baseline: 1.0316x; 1.0316x over previous
#include <cuda_runtime.h>
#include <cstdint>
#include <cstddef>

// Problem constants
#define BATCH 64
#define CH    512            // WIDTH == C_IN == 512
#define LSEQ  512
#define MAT   (CH * LSEQ)          // 262144 elems per [512,512] matrix
#define NMAT  (BATCH * MAT)        // 16777216 elems per [64,512,512] tensor

// ---------------- scratch (device globals; no allocation allowed) ------------
__device__ float g_Y[3ULL * NMAT];     // Q,K,V post-projection (192 MB)
__device__ float g_Wscore[NMAT];       // attention scores / weights (64 MB)
__device__ float g_X[2ULL * NMAT];     // ping-pong activations (128 MB)
__device__ float g_sum[3 * CH];
__device__ float g_sq[3 * CH];
__device__ float g_mean[3 * CH];
__device__ float g_rstd[3 * CH];

// packed f32x2 helpers (FFMA2 path — Blackwell dual-issue fp32)
__device__ __forceinline__ unsigned long long pack2(float a, float b) {
    unsigned long long r;
    asm("mov.b64 %0, {%1, %2};" : "=l"(r) : "f"(a), "f"(b));
    return r;
}
__device__ __forceinline__ void unpack2(unsigned long long p, float& a, float& b) {
    asm("mov.b64 {%0, %1}, %2;" : "=f"(a), "=f"(b) : "l"(p));
}
__device__ __forceinline__ void ffma2(unsigned long long& d,
                                      unsigned long long a, unsigned long long b) {
    asm("fma.rn.f32x2 %0, %1, %2, %0;" : "+l"(d) : "l"(a), "l"(b));
}

// ---------------- GEMM: C[b] = A (opt batched) * op(B[b]) -------------------
// M=N=K=512 fixed. Tile 128x128x16, 256 threads, 8x8 per thread (as 8x4 f32x2).
// TRANSB=false: B is [K][N] row-major (projection: X[b], out: V[b])
// TRANSB=true : B is [N][K] row-major (attention: K[b], dot over L)
// STATS=true  : add bias[row], accumulate per-row sum / sumsq via atomics.
#define TK 16
#define ASLD 132

template<bool TRANSB, bool STATS>
__launch_bounds__(256)
__global__ void gemm512(const float* __restrict__ A, int batchedA,
                        const float* __restrict__ Bm,
                        float* __restrict__ C,
                        const float* __restrict__ bias,
                        float* __restrict__ sums,
                        float* __restrict__ sqs)
{
    constexpr int BSLD = TRANSB ? 132 : 128;
    __shared__ float As[2][TK][ASLD];
    __shared__ float Bs[2][TK][BSLD];

    const int tid = threadIdx.x;
    const int tx  = tid & 15;
    const int ty  = tid >> 4;
    const int m0  = blockIdx.y * 128;
    const int n0  = blockIdx.x * 128;
    const int b   = blockIdx.z;

    const float* Ab = A  + (batchedA ? (size_t)b * MAT : 0);
    const float* Bb = Bm + (size_t)b * MAT;
    float*       Cb = C  + (size_t)b * MAT;

    // A loader: 128 rows x 16 k, row-major [M][K]; store transposed to As[k][m]
    const int la_r = tid >> 2;          // 0..63 (+64 on 2nd pass)
    const int la_c = (tid & 3) * 4;     // 0,4,8,12
    const float* Ap = Ab + (size_t)(m0 + la_r) * CH + la_c;

    // B loader
    const float* Bp = nullptr;
    int lb_r = 0, lb_c = 0;
    if (TRANSB) {
        Bp = Bb + (size_t)(n0 + la_r) * CH + la_c;          // [N][K] rows
    } else {
        lb_r = tid >> 5;                                    // 0..7 (+8)
        lb_c = (tid & 31) * 4;                              // 0..124
        Bp = Bb + (size_t)lb_r * LSEQ + n0 + lb_c;          // [K][N] rows
    }

    float4 aR0, aR1, bR0, bR1;

    auto ldg = [&](int kt) {
        aR0 = *(const float4*)(Ap + kt * TK);
        aR1 = *(const float4*)(Ap + 64 * CH + kt * TK);
        if (TRANSB) {
            bR0 = *(const float4*)(Bp + kt * TK);
            bR1 = *(const float4*)(Bp + 64 * CH + kt * TK);
        } else {
            bR0 = *(const float4*)(Bp + (size_t)kt * TK * LSEQ);
            bR1 = *(const float4*)(Bp + (size_t)kt * TK * LSEQ + 8 * LSEQ);
        }
    };
    auto sts = [&](int buf) {
        As[buf][la_c + 0][la_r]      = aR0.x;
        As[buf][la_c + 1][la_r]      = aR0.y;
        As[buf][la_c + 2][la_r]      = aR0.z;
        As[buf][la_c + 3][la_r]      = aR0.w;
        As[buf][la_c + 0][la_r + 64] = aR1.x;
        As[buf][la_c + 1][la_r + 64] = aR1.y;
        As[buf][la_c + 2][la_r + 64] = aR1.z;
        As[buf][la_c + 3][la_r + 64] = aR1.w;
        if (TRANSB) {
            Bs[buf][la_c + 0][la_r]      = bR0.x;
            Bs[buf][la_c + 1][la_r]      = bR0.y;
            Bs[buf][la_c + 2][la_r]      = bR0.z;
            Bs[buf][la_c + 3][la_r]      = bR0.w;
            Bs[buf][la_c + 0][la_r + 64] = bR1.x;
            Bs[buf][la_c + 1][la_r + 64] = bR1.y;
            Bs[buf][la_c + 2][la_r + 64] = bR1.z;
            Bs[buf][la_c + 3][la_r + 64] = bR1.w;
        } else {
            *(float4*)&Bs[buf][lb_r][lb_c]     = bR0;
            *(float4*)&Bs[buf][lb_r + 8][lb_c] = bR1;
        }
    };

    unsigned long long acc[8][4];
#pragma unroll
    for (int i = 0; i < 8; i++)
#pragma unroll
        for (int j = 0; j < 4; j++) acc[i][j] = 0ULL;   // (0.0f, 0.0f)

    ldg(0);
    sts(0);
    __syncthreads();

    for (int kt = 0; kt < 32; ++kt) {
        const int cur = kt & 1;
        if (kt < 31) ldg(kt + 1);
#pragma unroll
        for (int k = 0; k < TK; ++k) {
            float af[8];
            *(float4*)(af)     = *(const float4*)&As[cur][k][ty * 8];
            *(float4*)(af + 4) = *(const float4*)&As[cur][k][ty * 8 + 4];
            ulonglong2 bq0 = *(const ulonglong2*)&Bs[cur][k][tx * 8];
            ulonglong2 bq1 = *(const ulonglong2*)&Bs[cur][k][tx * 8 + 4];
            unsigned long long bp[4] = {bq0.x, bq0.y, bq1.x, bq1.y};
#pragma unroll
            for (int i = 0; i < 8; i++) {
                const unsigned long long ap = pack2(af[i], af[i]);
#pragma unroll
                for (int j = 0; j < 4; j++)
                    ffma2(acc[i][j], ap, bp[j]);
            }
        }
        if (kt < 31) sts(cur ^ 1);
        __syncthreads();
    }

    // epilogue
#pragma unroll
    for (int i = 0; i < 8; i++) {
        const int row = m0 + ty * 8 + i;
        float v[8];
#pragma unroll
        for (int j = 0; j < 4; j++) unpack2(acc[i][j], v[2 * j], v[2 * j + 1]);
        if (STATS) {
            const float bv = bias[row];
#pragma unroll
            for (int j = 0; j < 8; j++) v[j] += bv;
        }
        float4 v0 = make_float4(v[0], v[1], v[2], v[3]);
        float4 v1 = make_float4(v[4], v[5], v[6], v[7]);
        *(float4*)&Cb[(size_t)row * LSEQ + n0 + tx * 8]     = v0;
        *(float4*)&Cb[(size_t)row * LSEQ + n0 + tx * 8 + 4] = v1;
        if (STATS) {
            float s = 0.f, q = 0.f;
#pragma unroll
            for (int j = 0; j < 8; j++) { s += v[j]; q += v[j] * v[j]; }
#pragma unroll
            for (int off = 8; off > 0; off >>= 1) {
                s += __shfl_xor_sync(0xffffffffu, s, off);
                q += __shfl_xor_sync(0xffffffffu, q, off);
            }
            if (tx == 0) {
                atomicAdd(&sums[row], s);
                atomicAdd(&sqs[row], q);
            }
        }
    }
}

// ---------------- small kernels ----------------------------------------------
__global__ void zero_stats()
{
    int i = blockIdx.x * blockDim.x + threadIdx.x;
    if (i < 3 * CH) { g_sum[i] = 0.f; g_sq[i] = 0.f; }
}

__global__ void finalize_stats()
{
    int i = blockIdx.x * blockDim.x + threadIdx.x;
    if (i < 3 * CH) {
        const float inv_n = 1.0f / (float)(BATCH * LSEQ);
        float m = g_sum[i] * inv_n;
        float v = g_sq[i] * inv_n - m * m;
        g_mean[i] = m;
        g_rstd[i] = rsqrtf(v + 1e-5f);
    }
}

__global__ void bn_relu(float* __restrict__ Y, const float* __restrict__ gamma,
                        const float* __restrict__ beta, int statOff)
{
    size_t i = (size_t)blockIdx.x * blockDim.x + threadIdx.x;  // over NMAT/4
    float4* p = (float4*)Y;
    const int c = (int)((i >> 7) & 511);                       // channel (512 f = 128 f4 per row)
    const float m  = g_mean[statOff + c];
    const float r  = g_rstd[statOff + c];
    const float sc = r * gamma[c];
    const float sh = beta[c] - m * sc;
    float4 v = p[i];
    v.x = fmaxf(fmaf(v.x, sc, sh), 0.f);
    v.y = fmaxf(fmaf(v.y, sc, sh), 0.f);
    v.z = fmaxf(fmaf(v.z, sc, sh), 0.f);
    v.w = fmaxf(fmaf(v.w, sc, sh), 0.f);
    p[i] = v;
}

// softmax over the BATCH axis (dim 0): 64 values per (c,d), kept in registers
__global__ void softmax_batch(float* __restrict__ W)
{
    const int cd = blockIdx.x * blockDim.x + threadIdx.x;  // 0..262143
    float v[BATCH];
    float mx = -3.402823e38f;
#pragma unroll
    for (int b = 0; b < BATCH; b++) {
        v[b] = W[(size_t)b * MAT + cd];
        mx = fmaxf(mx, v[b]);
    }
    float s = 0.f;
#pragma unroll
    for (int b = 0; b < BATCH; b++) { v[b] = expf(v[b] - mx); s += v[b]; }
    const float r = 1.0f / s;
#pragma unroll
    for (int b = 0; b < BATCH; b++) W[(size_t)b * MAT + cd] = v[b] * r;
}

// ---------------- orchestration ----------------------------------------------
extern "C" void kernel_launch(void* const* d_in, const int* /*in_sizes*/, int /*n_in*/,
                              void* d_out, int /*out_size*/)
{
    const float* P     = (const float*)d_in[0];
    const float* Wq    = (const float*)d_in[1];
    const float* bq    = (const float*)d_in[2];
    const float* gq    = (const float*)d_in[3];
    const float* betaq = (const float*)d_in[4];
    const float* Wk    = (const float*)d_in[5];
    const float* bk    = (const float*)d_in[6];
    const float* gk    = (const float*)d_in[7];
    const float* betak = (const float*)d_in[8];
    const float* Wv    = (const float*)d_in[9];
    const float* bv    = (const float*)d_in[10];
    const float* gv    = (const float*)d_in[11];
    const float* betav = (const float*)d_in[12];

    float *Y, *Wsc, *X, *sum, *sq;
    cudaGetSymbolAddress((void**)&Y,   g_Y);
    cudaGetSymbolAddress((void**)&Wsc, g_Wscore);
    cudaGetSymbolAddress((void**)&X,   g_X);
    cudaGetSymbolAddress((void**)&sum, g_sum);
    cudaGetSymbolAddress((void**)&sq,  g_sq);

    const dim3 gg(4, 4, BATCH);

    for (int d = 0; d < 3; d++) {
        const float* xin  = (d == 0) ? P : X + (size_t)(d - 1) * NMAT;
        float*       xout = (d == 2) ? (float*)d_out : X + (size_t)d * NMAT;

        const float* Ws[3] = {Wq + (size_t)d * MAT, Wk + (size_t)d * MAT, Wv + (size_t)d * MAT};
        const float* bs[3] = {bq + d * CH, bk + d * CH, bv + d * CH};
        const float* gs[3] = {gq + d * CH, gk + d * CH, gv + d * CH};
        const float* be[3] = {betaq + d * CH, betak + d * CH, betav + d * CH};

        zero_stats<<<6, 256>>>();

        for (int p = 0; p < 3; p++)
            gemm512<false, true><<<gg, 256>>>(Ws[p], 0, xin, Y + (size_t)p * NMAT,
                                              bs[p], sum + p * CH, sq + p * CH);

        finalize_stats<<<6, 256>>>();

        for (int p = 0; p < 3; p++)
            bn_relu<<<NMAT / 4 / 256, 256>>>(Y + (size_t)p * NMAT, gs[p], be[p], p * CH);

        // scores: w[b] = Q[b] * K[b]^T   (dot over L)
        gemm512<true, false><<<gg, 256>>>(Y, 1, Y + (size_t)1 * NMAT, Wsc,
                                          nullptr, nullptr, nullptr);

        softmax_batch<<<MAT / 256, 256>>>(Wsc);

        // x = a[b] * V[b]
        gemm512<false, false><<<gg, 256>>>(Wsc, 1, Y + (size_t)2 * NMAT, xout,
                                           nullptr, nullptr, nullptr);
    }
}

// round 4
// speedup vs baseline: 1.5934x; 1.5447x over previous
#include <cuda_runtime.h>
#include <cuda_bf16.h>
#include <cstdint>
#include <cstddef>

#define BATCH 64
#define CH    512
#define LSEQ  512
#define MAT   (CH * LSEQ)
#define NMAT  (BATCH * MAT)

// ---------------- scratch -----------------------------------------------------
__device__ float g_Y[3ULL * NMAT];     // Q, K, VT
__device__ float g_Wsc[NMAT];          // scores
__device__ float g_X[2ULL * NMAT];     // xT ping-pong
__device__ float g_sum[3 * CH];
__device__ float g_sq[3 * CH];
__device__ float g_mean[3 * CH];
__device__ float g_rstd[3 * CH];

// ---------------- bf16 helpers -------------------------------------------------
__device__ __forceinline__ uint32_t packbf(float a, float b) {
    __nv_bfloat162 t = __floats2bfloat162_rn(a, b);   // x=a (low), y=b (high)
    return *reinterpret_cast<uint32_t*>(&t);
}
__device__ __forceinline__ float bf16rt(float x) {
    return __bfloat162float(__float2bfloat16(x));
}

#define LDSM4(R, addr) \
    asm volatile("ldmatrix.sync.aligned.m8n8.x4.shared.b16 {%0,%1,%2,%3}, [%4];" \
        : "=r"((R)[0]), "=r"((R)[1]), "=r"((R)[2]), "=r"((R)[3]) : "r"(addr))

__device__ __forceinline__ void mma16816(float* d, const uint32_t* a,
                                         uint32_t b0, uint32_t b1) {
    asm volatile(
        "mma.sync.aligned.m16n8k16.row.col.f32.bf16.bf16.f32 "
        "{%0,%1,%2,%3}, {%4,%5,%6,%7}, {%8,%9}, {%0,%1,%2,%3};"
        : "+f"(d[0]), "+f"(d[1]), "+f"(d[2]), "+f"(d[3])
        : "r"(a[0]), "r"(a[1]), "r"(a[2]), "r"(a[3]), "r"(b0), "r"(b1));
}

// ---------------- bf16x3 GEMM (NT): D[m][n] = sum_k A[m][k] B[n][k] -----------
// 512x512x512 per batch. CTA tile 128x128, 8 warps of 64x32, K-chunk 32.
// STATS: 0 none, 1 bias+stats per M-row, 2 bias+stats per N-col
#define KC 32
#define ROW_U32 20                    // 40 bf16 per row (32 used + 8 pad) -> conflict-free ldmatrix
#define TILE_U32 (128 * ROW_U32)      // 2560 u32 = 10240 B per tile
#define SMEM_DYN (2 * 4 * TILE_U32 * 4)   // 2 buffers x {Ah,Al,Bh,Bl} = 81920 B

template<int STATS>
__global__ __launch_bounds__(256, 2) void gemm_bf3(
    const float* __restrict__ A, int strideA,
    const float* __restrict__ B, int strideB,
    float* __restrict__ C,
    const float* __restrict__ bias,
    float* __restrict__ sums, float* __restrict__ sqs)
{
    extern __shared__ uint32_t sm[];
    const int tid  = threadIdx.x;
    const int lane = tid & 31, wid = tid >> 5;
    const int m0 = blockIdx.y * 128, n0 = blockIdx.x * 128, b = blockIdx.z;

    const float* Ab = A + (size_t)b * strideA;
    const float* Bb = B + (size_t)b * strideB;
    float*       Cb = C + (size_t)b * MAT;

    // loader coords: thread covers one 16-float half-row
    const int r = tid >> 1, h = tid & 1;
    const float* Ap = Ab + (size_t)(m0 + r) * 512 + h * 16;
    const float* Bp = Bb + (size_t)(n0 + r) * 512 + h * 16;
    const int stIdx = r * ROW_U32 + h * 8;

    // warp tiling
    const int mw = (wid & 1) * 64;
    const int nw = (wid >> 1) * 32;
    // per-lane ldmatrix addressing
    const int lrow = (lane & 7) + 8 * ((lane >> 3) & 1);
    const int lk16 = lane >> 4;                   // selects 16B k-half
    const uint32_t smembase = (uint32_t)__cvta_generic_to_shared(sm);
    const uint32_t aoffb = (uint32_t)((mw + lrow) * ROW_U32 + lk16 * 4);
    const uint32_t boffb = (uint32_t)((nw + lrow) * ROW_U32 + lk16 * 4);

    float acc[4][4][4];
#pragma unroll
    for (int i = 0; i < 4; i++)
#pragma unroll
        for (int j = 0; j < 4; j++)
#pragma unroll
            for (int e = 0; e < 4; e++) acc[i][j][e] = 0.f;

    float4 pf[8];

    auto ldg = [&](int c) {
        const int kc = c * KC;
#pragma unroll
        for (int q = 0; q < 4; q++) pf[q]     = *(const float4*)(Ap + kc + 4 * q);
#pragma unroll
        for (int q = 0; q < 4; q++) pf[4 + q] = *(const float4*)(Bp + kc + 4 * q);
    };

    auto cvt8 = [&](const float4* v, uint32_t* hi, uint32_t* lo) {
#pragma unroll
        for (int q = 0; q < 4; q++) {
            float4 x = v[q];
            hi[2 * q]     = packbf(x.x, x.y);
            hi[2 * q + 1] = packbf(x.z, x.w);
            lo[2 * q]     = packbf(x.x - bf16rt(x.x), x.y - bf16rt(x.y));
            lo[2 * q + 1] = packbf(x.z - bf16rt(x.z), x.w - bf16rt(x.w));
        }
    };

    auto sts = [&](int buf) {
        uint32_t* base = sm + buf * 4 * TILE_U32;
        uint32_t hi[8], lo[8];
        cvt8(pf, hi, lo);
        *(uint4*)(base + stIdx)                = make_uint4(hi[0], hi[1], hi[2], hi[3]);
        *(uint4*)(base + stIdx + 4)            = make_uint4(hi[4], hi[5], hi[6], hi[7]);
        *(uint4*)(base + TILE_U32 + stIdx)     = make_uint4(lo[0], lo[1], lo[2], lo[3]);
        *(uint4*)(base + TILE_U32 + stIdx + 4) = make_uint4(lo[4], lo[5], lo[6], lo[7]);
        cvt8(pf + 4, hi, lo);
        *(uint4*)(base + 2 * TILE_U32 + stIdx)     = make_uint4(hi[0], hi[1], hi[2], hi[3]);
        *(uint4*)(base + 2 * TILE_U32 + stIdx + 4) = make_uint4(hi[4], hi[5], hi[6], hi[7]);
        *(uint4*)(base + 3 * TILE_U32 + stIdx)     = make_uint4(lo[0], lo[1], lo[2], lo[3]);
        *(uint4*)(base + 3 * TILE_U32 + stIdx + 4) = make_uint4(lo[4], lo[5], lo[6], lo[7]);
    };

    auto compute = [&](int buf) {
        const uint32_t bb = smembase + 4u * (uint32_t)(buf * 4 * TILE_U32);
#pragma unroll
        for (int kg = 0; kg < 2; kg++) {
            uint32_t Af[4][4], Bh[2][4], Bl[2][4];
            const uint32_t kgo = 4u * (uint32_t)(kg * 8);
#pragma unroll
            for (int fi = 0; fi < 4; fi++)
                LDSM4(Af[fi], bb + 4u * (aoffb + fi * 16 * ROW_U32) + kgo);
#pragma unroll
            for (int bj = 0; bj < 2; bj++)
                LDSM4(Bh[bj], bb + 4u * (2 * TILE_U32 + boffb + bj * 16 * ROW_U32) + kgo);
            // hi * hi
#pragma unroll
            for (int i = 0; i < 4; i++)
#pragma unroll
                for (int j = 0; j < 4; j++)
                    mma16816(acc[i][j], Af[i], Bh[j >> 1][j & 1], Bh[j >> 1][(j & 1) + 2]);
            // hi * lo
#pragma unroll
            for (int bj = 0; bj < 2; bj++)
                LDSM4(Bl[bj], bb + 4u * (3 * TILE_U32 + boffb + bj * 16 * ROW_U32) + kgo);
#pragma unroll
            for (int i = 0; i < 4; i++)
#pragma unroll
                for (int j = 0; j < 4; j++)
                    mma16816(acc[i][j], Af[i], Bl[j >> 1][j & 1], Bl[j >> 1][(j & 1) + 2]);
            // lo * hi
#pragma unroll
            for (int fi = 0; fi < 4; fi++)
                LDSM4(Af[fi], bb + 4u * (TILE_U32 + aoffb + fi * 16 * ROW_U32) + kgo);
#pragma unroll
            for (int i = 0; i < 4; i++)
#pragma unroll
                for (int j = 0; j < 4; j++)
                    mma16816(acc[i][j], Af[i], Bh[j >> 1][j & 1], Bh[j >> 1][(j & 1) + 2]);
        }
    };

    ldg(0);
    sts(0);
    __syncthreads();

#pragma unroll 1
    for (int c = 0; c < 16; c++) {
        if (c < 15) ldg(c + 1);
        compute(c & 1);
        if (c < 15) sts((c + 1) & 1);
        __syncthreads();
    }

    // ---------------- epilogue ----------------
    const int rg = lane >> 2;
    const int cg = (lane & 3) * 2;

    float bc[8];
    if (STATS == 2) {
#pragma unroll
        for (int j = 0; j < 4; j++) {
            bc[2 * j]     = bias[n0 + nw + j * 8 + cg];
            bc[2 * j + 1] = bias[n0 + nw + j * 8 + cg + 1];
        }
    }
    float cs[8], cq[8];
    if (STATS == 2) {
#pragma unroll
        for (int e = 0; e < 8; e++) { cs[e] = 0.f; cq[e] = 0.f; }
    }

#pragma unroll
    for (int i = 0; i < 4; i++) {
        const int row0 = m0 + mw + i * 16 + rg;
        const int row1 = row0 + 8;
        float bv0 = 0.f, bv1 = 0.f;
        if (STATS == 1) { bv0 = bias[row0]; bv1 = bias[row1]; }
        float s0 = 0.f, q0 = 0.f, s1 = 0.f, q1 = 0.f;
#pragma unroll
        for (int j = 0; j < 4; j++) {
            float* cc = acc[i][j];
            if (STATS == 1) { cc[0] += bv0; cc[1] += bv0; cc[2] += bv1; cc[3] += bv1; }
            if (STATS == 2) {
                cc[0] += bc[2 * j]; cc[1] += bc[2 * j + 1];
                cc[2] += bc[2 * j]; cc[3] += bc[2 * j + 1];
            }
            const int col = n0 + nw + j * 8 + cg;
            *(float2*)&Cb[(size_t)row0 * 512 + col] = make_float2(cc[0], cc[1]);
            *(float2*)&Cb[(size_t)row1 * 512 + col] = make_float2(cc[2], cc[3]);
            if (STATS == 1) {
                s0 += cc[0] + cc[1]; q0 += cc[0] * cc[0] + cc[1] * cc[1];
                s1 += cc[2] + cc[3]; q1 += cc[2] * cc[2] + cc[3] * cc[3];
            }
            if (STATS == 2) {
                cs[2 * j]     += cc[0] + cc[2];
                cs[2 * j + 1] += cc[1] + cc[3];
                cq[2 * j]     += cc[0] * cc[0] + cc[2] * cc[2];
                cq[2 * j + 1] += cc[1] * cc[1] + cc[3] * cc[3];
            }
        }
        if (STATS == 1) {
#pragma unroll
            for (int off = 1; off <= 2; off <<= 1) {
                s0 += __shfl_xor_sync(0xffffffffu, s0, off);
                q0 += __shfl_xor_sync(0xffffffffu, q0, off);
                s1 += __shfl_xor_sync(0xffffffffu, s1, off);
                q1 += __shfl_xor_sync(0xffffffffu, q1, off);
            }
            if ((lane & 3) == 0) {
                atomicAdd(&sums[row0], s0); atomicAdd(&sqs[row0], q0);
                atomicAdd(&sums[row1], s1); atomicAdd(&sqs[row1], q1);
            }
        }
    }
    if (STATS == 2) {
#pragma unroll
        for (int e = 0; e < 8; e++) {
#pragma unroll
            for (int off = 4; off <= 16; off <<= 1) {
                cs[e] += __shfl_xor_sync(0xffffffffu, cs[e], off);
                cq[e] += __shfl_xor_sync(0xffffffffu, cq[e], off);
            }
        }
        if (rg == 0) {
#pragma unroll
            for (int j = 0; j < 4; j++) {
                const int col = n0 + nw + j * 8 + cg;
                atomicAdd(&sums[col], cs[2 * j]);     atomicAdd(&sqs[col], cq[2 * j]);
                atomicAdd(&sums[col + 1], cs[2 * j + 1]); atomicAdd(&sqs[col + 1], cq[2 * j + 1]);
            }
        }
    }
}

// ---------------- small kernels ------------------------------------------------
__global__ void transposeCL(const float* __restrict__ src, float* __restrict__ dst)
{
    __shared__ float t[32][33];
    const int b = blockIdx.z;
    const int x0 = blockIdx.x * 32;
    const int y0 = blockIdx.y * 32;
    const float* S = src + (size_t)b * MAT;
    float*       D = dst + (size_t)b * MAT;
    const int tx = threadIdx.x, ty = threadIdx.y;
#pragma unroll
    for (int j = 0; j < 32; j += 8)
        t[ty + j][tx] = S[(size_t)(y0 + ty + j) * 512 + x0 + tx];
    __syncthreads();
#pragma unroll
    for (int j = 0; j < 32; j += 8)
        D[(size_t)(x0 + ty + j) * 512 + y0 + tx] = t[tx][ty + j];
}

__global__ void zero_stats()
{
    int i = blockIdx.x * blockDim.x + threadIdx.x;
    if (i < 3 * CH) { g_sum[i] = 0.f; g_sq[i] = 0.f; }
}

__global__ void finalize_stats()
{
    int i = blockIdx.x * blockDim.x + threadIdx.x;
    if (i < 3 * CH) {
        const float inv_n = 1.0f / (float)(BATCH * LSEQ);
        float m = g_sum[i] * inv_n;
        float v = g_sq[i] * inv_n - m * m;
        g_mean[i] = m;
        g_rstd[i] = rsqrtf(v + 1e-5f);
    }
}

// channel = row (layout [c][l])
__global__ void bn_relu_row(float* __restrict__ Y, const float* __restrict__ gamma,
                            const float* __restrict__ beta, int statOff)
{
    size_t i = (size_t)blockIdx.x * blockDim.x + threadIdx.x;
    float4* p = (float4*)Y;
    const int c = (int)((i >> 7) & 511);
    const float m  = g_mean[statOff + c];
    const float rs = g_rstd[statOff + c];
    const float sc = rs * gamma[c];
    const float sh = beta[c] - m * sc;
    float4 v = p[i];
    v.x = fmaxf(fmaf(v.x, sc, sh), 0.f);
    v.y = fmaxf(fmaf(v.y, sc, sh), 0.f);
    v.z = fmaxf(fmaf(v.z, sc, sh), 0.f);
    v.w = fmaxf(fmaf(v.w, sc, sh), 0.f);
    p[i] = v;
}

// channel = fastest dim (layout [l][c])
__global__ void bn_relu_col(float* __restrict__ Y, const float* __restrict__ gamma,
                            const float* __restrict__ beta, int statOff)
{
    size_t i = (size_t)blockIdx.x * blockDim.x + threadIdx.x;
    float4* p = (float4*)Y;
    const int c4 = (int)(i & 127);
    const float4 g  = ((const float4*)gamma)[c4];
    const float4 be = ((const float4*)beta)[c4];
    const float4 m  = *(const float4*)(g_mean + statOff + c4 * 4);
    const float4 rs = *(const float4*)(g_rstd + statOff + c4 * 4);
    float4 v = p[i];
    v.x = fmaxf(fmaf(v.x, rs.x * g.x, be.x - m.x * rs.x * g.x), 0.f);
    v.y = fmaxf(fmaf(v.y, rs.y * g.y, be.y - m.y * rs.y * g.y), 0.f);
    v.z = fmaxf(fmaf(v.z, rs.z * g.z, be.z - m.z * rs.z * g.z), 0.f);
    v.w = fmaxf(fmaf(v.w, rs.w * g.w, be.w - m.w * rs.w * g.w), 0.f);
    p[i] = v;
}

__global__ void softmax_batch(float* __restrict__ W)
{
    const int cd = blockIdx.x * blockDim.x + threadIdx.x;
    float v[BATCH];
    float mx = -3.402823e38f;
#pragma unroll
    for (int b = 0; b < BATCH; b++) {
        v[b] = W[(size_t)b * MAT + cd];
        mx = fmaxf(mx, v[b]);
    }
    float s = 0.f;
#pragma unroll
    for (int b = 0; b < BATCH; b++) { v[b] = expf(v[b] - mx); s += v[b]; }
    const float r = 1.0f / s;
#pragma unroll
    for (int b = 0; b < BATCH; b++) W[(size_t)b * MAT + cd] = v[b] * r;
}

// ---------------- orchestration -------------------------------------------------
extern "C" void kernel_launch(void* const* d_in, const int* /*in_sizes*/, int /*n_in*/,
                              void* d_out, int /*out_size*/)
{
    const float* P     = (const float*)d_in[0];
    const float* Wq    = (const float*)d_in[1];
    const float* bq    = (const float*)d_in[2];
    const float* gq    = (const float*)d_in[3];
    const float* betaq = (const float*)d_in[4];
    const float* Wk    = (const float*)d_in[5];
    const float* bk    = (const float*)d_in[6];
    const float* gk    = (const float*)d_in[7];
    const float* betak = (const float*)d_in[8];
    const float* Wv    = (const float*)d_in[9];
    const float* bv    = (const float*)d_in[10];
    const float* gv    = (const float*)d_in[11];
    const float* betav = (const float*)d_in[12];

    cudaFuncSetAttribute(gemm_bf3<0>, cudaFuncAttributeMaxDynamicSharedMemorySize, SMEM_DYN);
    cudaFuncSetAttribute(gemm_bf3<1>, cudaFuncAttributeMaxDynamicSharedMemorySize, SMEM_DYN);
    cudaFuncSetAttribute(gemm_bf3<2>, cudaFuncAttributeMaxDynamicSharedMemorySize, SMEM_DYN);

    float *Y, *Wsc, *X, *sum, *sq;
    cudaGetSymbolAddress((void**)&Y,   g_Y);
    cudaGetSymbolAddress((void**)&Wsc, g_Wsc);
    cudaGetSymbolAddress((void**)&X,   g_X);
    cudaGetSymbolAddress((void**)&sum, g_sum);
    cudaGetSymbolAddress((void**)&sq,  g_sq);

    float* Q  = Y;
    float* K  = Y + (size_t)NMAT;
    float* VT = Y + 2ULL * NMAT;

    const dim3 gg(4, 4, BATCH);

    // xT[0] = transpose(P)
    transposeCL<<<dim3(16, 16, BATCH), dim3(32, 8)>>>(P, X);

    for (int d = 0; d < 3; d++) {
        float* xinT = (d == 1) ? X + (size_t)NMAT : X;
        float* xout = (d == 0) ? X + (size_t)NMAT
                    : (d == 1) ? X
                               : (float*)d_out;

        const float* Wq_d = Wq + (size_t)d * MAT;
        const float* Wk_d = Wk + (size_t)d * MAT;
        const float* Wv_d = Wv + (size_t)d * MAT;

        zero_stats<<<6, 256>>>();

        // Q[c][l], K[c][l] : row-stats
        gemm_bf3<1><<<gg, 256, SMEM_DYN>>>(Wq_d, 0, xinT, MAT, Q, bq + d * CH, sum, sq);
        gemm_bf3<1><<<gg, 256, SMEM_DYN>>>(Wk_d, 0, xinT, MAT, K, bk + d * CH, sum + CH, sq + CH);
        // VT[l][d] : col-stats
        gemm_bf3<2><<<gg, 256, SMEM_DYN>>>(xinT, MAT, Wv_d, 0, VT, bv + d * CH, sum + 2 * CH, sq + 2 * CH);

        finalize_stats<<<6, 256>>>();

        bn_relu_row<<<NMAT / 4 / 256, 256>>>(Q, gq + d * CH, betaq + d * CH, 0);
        bn_relu_row<<<NMAT / 4 / 256, 256>>>(K, gk + d * CH, betak + d * CH, CH);
        bn_relu_col<<<NMAT / 4 / 256, 256>>>(VT, gv + d * CH, betav + d * CH, 2 * CH);

        // scores w[c][d] = sum_l Q[c][l] K[d][l]
        gemm_bf3<0><<<gg, 256, SMEM_DYN>>>(Q, MAT, K, MAT, Wsc, nullptr, nullptr, nullptr);

        softmax_batch<<<MAT / 256, 256>>>(Wsc);

        if (d < 2) {
            // xT_next[l][c] = sum_d VT[l][d] * w[c][d]
            gemm_bf3<0><<<gg, 256, SMEM_DYN>>>(VT, MAT, Wsc, MAT, xout, nullptr, nullptr, nullptr);
        } else {
            // out[c][l] = sum_d w[c][d] * VT[l][d]
            gemm_bf3<0><<<gg, 256, SMEM_DYN>>>(Wsc, MAT, VT, MAT, xout, nullptr, nullptr, nullptr);
        }
    }
}

// round 5
// speedup vs baseline: 2.2562x; 1.4159x over previous
#include <cuda_runtime.h>
#include <cuda_bf16.h>
#include <cstdint>
#include <cstddef>

#define BATCH 64
#define CH    512
#define LSEQ  512
#define MAT   (CH * LSEQ)
#define NMAT  (BATCH * MAT)

// ---------------- scratch -----------------------------------------------------
__device__ float    g_Y[3ULL * NMAT];        // Q,K,VT pre-BN fp32
__device__ float    g_Wsc[NMAT];             // scores fp32
// bf16 hi/lo tensors: QH,QL,KH,KL,VH,VL,WH,WL,X0H,X0L,X1H,X1L
__device__ uint16_t g_bf[12ULL * NMAT];
__device__ uint16_t g_wth[9ULL * MAT];       // weight hi: [q,k,v][depth][512][512]
__device__ uint16_t g_wtl[9ULL * MAT];
__device__ float g_sum[3 * CH];
__device__ float g_sq[3 * CH];
__device__ float g_mean[3 * CH];
__device__ float g_rstd[3 * CH];

// ---------------- helpers ------------------------------------------------------
__device__ __forceinline__ uint32_t packbf(float a, float b) {
    __nv_bfloat162 t = __floats2bfloat162_rn(a, b);
    return *reinterpret_cast<uint32_t*>(&t);
}
__device__ __forceinline__ float bf16rt(float x) {
    return __bfloat162float(__float2bfloat16(x));
}

#define LDSM4(R, addr) \
    asm volatile("ldmatrix.sync.aligned.m8n8.x4.shared.b16 {%0,%1,%2,%3}, [%4];" \
        : "=r"((R)[0]), "=r"((R)[1]), "=r"((R)[2]), "=r"((R)[3]) : "r"(addr))

__device__ __forceinline__ void mma16816(float* d, const uint32_t* a,
                                         uint32_t b0, uint32_t b1) {
    asm volatile(
        "mma.sync.aligned.m16n8k16.row.col.f32.bf16.bf16.f32 "
        "{%0,%1,%2,%3}, {%4,%5,%6,%7}, {%8,%9}, {%0,%1,%2,%3};"
        : "+f"(d[0]), "+f"(d[1]), "+f"(d[2]), "+f"(d[3])
        : "r"(a[0]), "r"(a[1]), "r"(a[2]), "r"(a[3]), "r"(b0), "r"(b1));
}

#define CP16(dst, src) \
    asm volatile("cp.async.cg.shared.global [%0], [%1], 16;" :: "r"(dst), "l"(src))
#define CPCOMMIT() asm volatile("cp.async.commit_group;" ::: "memory")
#define CPWAIT1()  asm volatile("cp.async.wait_group 1;" ::: "memory")

// ---------------- GEMM (NT, bf16x3, pre-split operands) ------------------------
// D[m][n] = sum_k A[m][k]*B[n][k], 512^3 per batch, A/B given as bf16 hi+lo.
// CTA tile 128x128, 8 warps of 64x32, K-chunk 32, 3-stage cp.async pipeline.
// OUT: 0=fp32, 1=fp32+bias+rowstats, 2=fp32+bias+colstats, 3=bf16 hi/lo split.
#define KC 32
#define STAGE_B 32768                    // 4 tiles x 8192 B
#define TILE_B  8192                     // 128 rows x 64 B
#define SMEM_DYN (3 * STAGE_B)           // 98304

template<int OUT>
__global__ __launch_bounds__(256, 2) void gemm_bf3(
    const uint16_t* __restrict__ Ah, const uint16_t* __restrict__ Al, int strideA,
    const uint16_t* __restrict__ Bh, const uint16_t* __restrict__ Bl, int strideB,
    float* __restrict__ Cf,
    uint16_t* __restrict__ Ch, uint16_t* __restrict__ Cl,
    const float* __restrict__ bias,
    float* __restrict__ sums, float* __restrict__ sqs)
{
    extern __shared__ uint8_t smraw[];
    const uint32_t smemu = (uint32_t)__cvta_generic_to_shared(smraw);
    const int tid  = threadIdx.x;
    const int lane = tid & 31, wid = tid >> 5;
    const int m0 = blockIdx.y * 128, n0 = blockIdx.x * 128, b = blockIdx.z;

    const size_t oa = (size_t)b * strideA;
    const size_t ob = (size_t)b * strideB;

    // ---- loader: each thread owns 2 x 16B chunks per tile component
    const int id0 = tid, id1 = tid + 256;
    const int r0 = id0 >> 2, k0 = id0 & 3;
    const int r1 = id1 >> 2, k1 = id1 & 3;
    const uint32_t dst0 = (uint32_t)(r0 * 64 + ((k0 ^ ((r0 >> 1) & 3)) << 4));
    const uint32_t dst1 = (uint32_t)(r1 * 64 + ((k1 ^ ((r1 >> 1) & 3)) << 4));
    const char* aH0 = (const char*)(Ah + oa + (size_t)(m0 + r0) * 512 + k0 * 8);
    const char* aL0 = (const char*)(Al + oa + (size_t)(m0 + r0) * 512 + k0 * 8);
    const char* bH0 = (const char*)(Bh + ob + (size_t)(n0 + r0) * 512 + k0 * 8);
    const char* bL0 = (const char*)(Bl + ob + (size_t)(n0 + r0) * 512 + k0 * 8);
    const char* aH1 = (const char*)(Ah + oa + (size_t)(m0 + r1) * 512 + k1 * 8);
    const char* aL1 = (const char*)(Al + oa + (size_t)(m0 + r1) * 512 + k1 * 8);
    const char* bH1 = (const char*)(Bh + ob + (size_t)(n0 + r1) * 512 + k1 * 8);
    const char* bL1 = (const char*)(Bl + ob + (size_t)(n0 + r1) * 512 + k1 * 8);

    auto issue = [&](int s, int c) {
        const uint32_t sb = smemu + (uint32_t)s * STAGE_B;
        const size_t o = (size_t)c * (KC * 2);
        CP16(sb + dst0,              aH0 + o);
        CP16(sb + TILE_B + dst0,     aL0 + o);
        CP16(sb + 2 * TILE_B + dst0, bH0 + o);
        CP16(sb + 3 * TILE_B + dst0, bL0 + o);
        CP16(sb + dst1,              aH1 + o);
        CP16(sb + TILE_B + dst1,     aL1 + o);
        CP16(sb + 2 * TILE_B + dst1, bH1 + o);
        CP16(sb + 3 * TILE_B + dst1, bL1 + o);
    };

    // ---- compute-side per-lane ldmatrix offsets (precomputed)
    const int mw = (wid & 1) * 64;
    const int nw = (wid >> 1) * 32;
    const int lrow = (lane & 7) + 8 * ((lane >> 3) & 1);
    const int lk16 = lane >> 4;
    uint32_t offA[4][2], offB[2][2];
#pragma unroll
    for (int fi = 0; fi < 4; fi++) {
        const int row = mw + fi * 16 + lrow;
        const uint32_t sw = (row >> 1) & 3;
        offA[fi][0] = (uint32_t)(row * 64 + (((0 + lk16) ^ sw) << 4));
        offA[fi][1] = (uint32_t)(row * 64 + (((2 + lk16) ^ sw) << 4));
    }
#pragma unroll
    for (int bj = 0; bj < 2; bj++) {
        const int row = nw + bj * 16 + lrow;
        const uint32_t sw = (row >> 1) & 3;
        offB[bj][0] = (uint32_t)(row * 64 + (((0 + lk16) ^ sw) << 4));
        offB[bj][1] = (uint32_t)(row * 64 + (((2 + lk16) ^ sw) << 4));
    }

    float acc[4][4][4];
#pragma unroll
    for (int i = 0; i < 4; i++)
#pragma unroll
        for (int j = 0; j < 4; j++)
#pragma unroll
            for (int e = 0; e < 4; e++) acc[i][j][e] = 0.f;

    auto compute = [&](int s) {
        const uint32_t sb = smemu + (uint32_t)s * STAGE_B;
#pragma unroll
        for (int kg = 0; kg < 2; kg++) {
            uint32_t Af[4][4], Bh2[2][4], Bl2[2][4];
#pragma unroll
            for (int fi = 0; fi < 4; fi++)
                LDSM4(Af[fi], sb + offA[fi][kg]);
#pragma unroll
            for (int bj = 0; bj < 2; bj++)
                LDSM4(Bh2[bj], sb + 2 * TILE_B + offB[bj][kg]);
#pragma unroll
            for (int i = 0; i < 4; i++)
#pragma unroll
                for (int j = 0; j < 4; j++)
                    mma16816(acc[i][j], Af[i], Bh2[j >> 1][j & 1], Bh2[j >> 1][(j & 1) + 2]);
#pragma unroll
            for (int bj = 0; bj < 2; bj++)
                LDSM4(Bl2[bj], sb + 3 * TILE_B + offB[bj][kg]);
#pragma unroll
            for (int i = 0; i < 4; i++)
#pragma unroll
                for (int j = 0; j < 4; j++)
                    mma16816(acc[i][j], Af[i], Bl2[j >> 1][j & 1], Bl2[j >> 1][(j & 1) + 2]);
#pragma unroll
            for (int fi = 0; fi < 4; fi++)
                LDSM4(Af[fi], sb + TILE_B + offA[fi][kg]);
#pragma unroll
            for (int i = 0; i < 4; i++)
#pragma unroll
                for (int j = 0; j < 4; j++)
                    mma16816(acc[i][j], Af[i], Bh2[j >> 1][j & 1], Bh2[j >> 1][(j & 1) + 2]);
        }
    };

    issue(0, 0); CPCOMMIT();
    issue(1, 1); CPCOMMIT();

#pragma unroll 1
    for (int c = 0; c < 16; c++) {
        CPWAIT1();
        __syncthreads();
        if (c + 2 < 16) issue((c + 2) % 3, c + 2);
        CPCOMMIT();
        compute(c % 3);
    }

    // ---------------- epilogue ----------------
    const int rg = lane >> 2;
    const int cg = (lane & 3) * 2;
    float* CfB = Cf + (size_t)b * MAT;

    float bc[8];
    if (OUT == 2) {
#pragma unroll
        for (int j = 0; j < 4; j++) {
            bc[2 * j]     = bias[n0 + nw + j * 8 + cg];
            bc[2 * j + 1] = bias[n0 + nw + j * 8 + cg + 1];
        }
    }
    float cs[8], cq[8];
    if (OUT == 2) {
#pragma unroll
        for (int e = 0; e < 8; e++) { cs[e] = 0.f; cq[e] = 0.f; }
    }

#pragma unroll
    for (int i = 0; i < 4; i++) {
        const int row0 = m0 + mw + i * 16 + rg;
        const int row1 = row0 + 8;
        float bv0 = 0.f, bv1 = 0.f;
        if (OUT == 1) { bv0 = bias[row0]; bv1 = bias[row1]; }
        float s0 = 0.f, q0 = 0.f, s1 = 0.f, q1 = 0.f;
#pragma unroll
        for (int j = 0; j < 4; j++) {
            float* cc = acc[i][j];
            if (OUT == 1) { cc[0] += bv0; cc[1] += bv0; cc[2] += bv1; cc[3] += bv1; }
            if (OUT == 2) {
                cc[0] += bc[2 * j]; cc[1] += bc[2 * j + 1];
                cc[2] += bc[2 * j]; cc[3] += bc[2 * j + 1];
            }
            const int col = n0 + nw + j * 8 + cg;
            if (OUT == 3) {
                uint32_t* H = (uint32_t*)(Ch + (size_t)b * MAT);
                uint32_t* L = (uint32_t*)(Cl + (size_t)b * MAT);
                const size_t i0 = ((size_t)row0 * 512 + col) >> 1;
                const size_t i1 = ((size_t)row1 * 512 + col) >> 1;
                H[i0] = packbf(cc[0], cc[1]);
                L[i0] = packbf(cc[0] - bf16rt(cc[0]), cc[1] - bf16rt(cc[1]));
                H[i1] = packbf(cc[2], cc[3]);
                L[i1] = packbf(cc[2] - bf16rt(cc[2]), cc[3] - bf16rt(cc[3]));
            } else {
                *(float2*)&CfB[(size_t)row0 * 512 + col] = make_float2(cc[0], cc[1]);
                *(float2*)&CfB[(size_t)row1 * 512 + col] = make_float2(cc[2], cc[3]);
            }
            if (OUT == 1) {
                s0 += cc[0] + cc[1]; q0 += cc[0] * cc[0] + cc[1] * cc[1];
                s1 += cc[2] + cc[3]; q1 += cc[2] * cc[2] + cc[3] * cc[3];
            }
            if (OUT == 2) {
                cs[2 * j]     += cc[0] + cc[2];
                cs[2 * j + 1] += cc[1] + cc[3];
                cq[2 * j]     += cc[0] * cc[0] + cc[2] * cc[2];
                cq[2 * j + 1] += cc[1] * cc[1] + cc[3] * cc[3];
            }
        }
        if (OUT == 1) {
#pragma unroll
            for (int off = 1; off <= 2; off <<= 1) {
                s0 += __shfl_xor_sync(0xffffffffu, s0, off);
                q0 += __shfl_xor_sync(0xffffffffu, q0, off);
                s1 += __shfl_xor_sync(0xffffffffu, s1, off);
                q1 += __shfl_xor_sync(0xffffffffu, q1, off);
            }
            if ((lane & 3) == 0) {
                atomicAdd(&sums[row0], s0); atomicAdd(&sqs[row0], q0);
                atomicAdd(&sums[row1], s1); atomicAdd(&sqs[row1], q1);
            }
        }
    }
    if (OUT == 2) {
#pragma unroll
        for (int e = 0; e < 8; e++) {
#pragma unroll
            for (int off = 4; off <= 16; off <<= 1) {
                cs[e] += __shfl_xor_sync(0xffffffffu, cs[e], off);
                cq[e] += __shfl_xor_sync(0xffffffffu, cq[e], off);
            }
        }
        if (rg == 0) {
#pragma unroll
            for (int j = 0; j < 4; j++) {
                const int col = n0 + nw + j * 8 + cg;
                atomicAdd(&sums[col], cs[2 * j]);         atomicAdd(&sqs[col], cq[2 * j]);
                atomicAdd(&sums[col + 1], cs[2 * j + 1]); atomicAdd(&sqs[col + 1], cq[2 * j + 1]);
            }
        }
    }
}

// ---------------- elementwise kernels -------------------------------------------
// transpose P [c][l] fp32 -> XT [l][c] bf16 hi/lo
__global__ void transpose_split(const float* __restrict__ src,
                                uint16_t* __restrict__ H, uint16_t* __restrict__ L)
{
    __shared__ float t[32][33];
    const int b = blockIdx.z;
    const int x0 = blockIdx.x * 32;   // l
    const int y0 = blockIdx.y * 32;   // c
    const float* S = src + (size_t)b * MAT;
    const int tx = threadIdx.x, ty = threadIdx.y;
#pragma unroll
    for (int j = 0; j < 32; j += 8)
        t[ty + j][tx] = S[(size_t)(y0 + ty + j) * 512 + x0 + tx];
    __syncthreads();
    uint16_t* Hb = H + (size_t)b * MAT;
    uint16_t* Lb = L + (size_t)b * MAT;
#pragma unroll
    for (int j = 0; j < 32; j += 8) {
        float v = t[tx][ty + j];
        float h = bf16rt(v);
        const size_t idx = (size_t)(x0 + ty + j) * 512 + y0 + tx;
        __nv_bfloat16 hb = __float2bfloat16(v);
        __nv_bfloat16 lb = __float2bfloat16(v - h);
        Hb[idx] = *reinterpret_cast<uint16_t*>(&hb);
        Lb[idx] = *reinterpret_cast<uint16_t*>(&lb);
    }
}

// fp32 -> bf16 hi/lo (weights)
__global__ void cvt_split(const float* __restrict__ src,
                          uint16_t* __restrict__ H, uint16_t* __restrict__ L)
{
    const size_t i = (size_t)blockIdx.x * blockDim.x + threadIdx.x;  // float4 idx
    float4 v = ((const float4*)src)[i];
    uint2 h, l;
    h.x = packbf(v.x, v.y);
    h.y = packbf(v.z, v.w);
    l.x = packbf(v.x - bf16rt(v.x), v.y - bf16rt(v.y));
    l.y = packbf(v.z - bf16rt(v.z), v.w - bf16rt(v.w));
    ((uint2*)H)[i] = h;
    ((uint2*)L)[i] = l;
}

__global__ void zero_stats()
{
    int i = blockIdx.x * blockDim.x + threadIdx.x;
    if (i < 3 * CH) { g_sum[i] = 0.f; g_sq[i] = 0.f; }
}

__global__ void finalize_stats()
{
    int i = blockIdx.x * blockDim.x + threadIdx.x;
    if (i < 3 * CH) {
        const float inv_n = 1.0f / (float)(BATCH * LSEQ);
        float m = g_sum[i] * inv_n;
        float v = g_sq[i] * inv_n - m * m;
        g_mean[i] = m;
        g_rstd[i] = rsqrtf(v + 1e-5f);
    }
}

// BN+ReLU for layout [c][l] (channel = row), emit bf16 hi/lo
__global__ void bn_relu_row_split(const float* __restrict__ Y,
                                  const float* __restrict__ gamma,
                                  const float* __restrict__ beta, int statOff,
                                  uint16_t* __restrict__ H, uint16_t* __restrict__ L)
{
    const size_t i = (size_t)blockIdx.x * blockDim.x + threadIdx.x;  // float4 idx
    const int c = (int)((i >> 7) & 511);
    const float m  = g_mean[statOff + c];
    const float rs = g_rstd[statOff + c];
    const float sc = rs * gamma[c];
    const float sh = beta[c] - m * sc;
    float4 v = ((const float4*)Y)[i];
    v.x = fmaxf(fmaf(v.x, sc, sh), 0.f);
    v.y = fmaxf(fmaf(v.y, sc, sh), 0.f);
    v.z = fmaxf(fmaf(v.z, sc, sh), 0.f);
    v.w = fmaxf(fmaf(v.w, sc, sh), 0.f);
    uint2 h, l;
    h.x = packbf(v.x, v.y); h.y = packbf(v.z, v.w);
    l.x = packbf(v.x - bf16rt(v.x), v.y - bf16rt(v.y));
    l.y = packbf(v.z - bf16rt(v.z), v.w - bf16rt(v.w));
    ((uint2*)H)[i] = h;
    ((uint2*)L)[i] = l;
}

// BN+ReLU for layout [l][c] (channel = fastest), emit bf16 hi/lo
__global__ void bn_relu_col_split(const float* __restrict__ Y,
                                  const float* __restrict__ gamma,
                                  const float* __restrict__ beta, int statOff,
                                  uint16_t* __restrict__ H, uint16_t* __restrict__ L)
{
    const size_t i = (size_t)blockIdx.x * blockDim.x + threadIdx.x;
    const int c4 = (int)(i & 127);
    const float4 g  = ((const float4*)gamma)[c4];
    const float4 be = ((const float4*)beta)[c4];
    const float4 m  = *(const float4*)(g_mean + statOff + c4 * 4);
    const float4 rs = *(const float4*)(g_rstd + statOff + c4 * 4);
    float4 v = ((const float4*)Y)[i];
    v.x = fmaxf(fmaf(v.x, rs.x * g.x, be.x - m.x * rs.x * g.x), 0.f);
    v.y = fmaxf(fmaf(v.y, rs.y * g.y, be.y - m.y * rs.y * g.y), 0.f);
    v.z = fmaxf(fmaf(v.z, rs.z * g.z, be.z - m.z * rs.z * g.z), 0.f);
    v.w = fmaxf(fmaf(v.w, rs.w * g.w, be.w - m.w * rs.w * g.w), 0.f);
    uint2 h, l;
    h.x = packbf(v.x, v.y); h.y = packbf(v.z, v.w);
    l.x = packbf(v.x - bf16rt(v.x), v.y - bf16rt(v.y));
    l.y = packbf(v.z - bf16rt(v.z), v.w - bf16rt(v.w));
    ((uint2*)H)[i] = h;
    ((uint2*)L)[i] = l;
}

// softmax over batch axis; emit bf16 hi/lo
__global__ void softmax_split(const float* __restrict__ W,
                              uint16_t* __restrict__ H, uint16_t* __restrict__ L)
{
    const int cd = blockIdx.x * blockDim.x + threadIdx.x;
    float v[BATCH];
    float mx = -3.402823e38f;
#pragma unroll
    for (int b = 0; b < BATCH; b++) {
        v[b] = W[(size_t)b * MAT + cd];
        mx = fmaxf(mx, v[b]);
    }
    float s = 0.f;
#pragma unroll
    for (int b = 0; b < BATCH; b++) { v[b] = expf(v[b] - mx); s += v[b]; }
    const float r = 1.0f / s;
#pragma unroll
    for (int b = 0; b < BATCH; b++) {
        const float z = v[b] * r;
        const float h = bf16rt(z);
        __nv_bfloat16 hb = __float2bfloat16(z);
        __nv_bfloat16 lb = __float2bfloat16(z - h);
        H[(size_t)b * MAT + cd] = *reinterpret_cast<uint16_t*>(&hb);
        L[(size_t)b * MAT + cd] = *reinterpret_cast<uint16_t*>(&lb);
    }
}

// ---------------- orchestration -------------------------------------------------
extern "C" void kernel_launch(void* const* d_in, const int* /*in_sizes*/, int /*n_in*/,
                              void* d_out, int /*out_size*/)
{
    const float* P     = (const float*)d_in[0];
    const float* Wq    = (const float*)d_in[1];
    const float* bq    = (const float*)d_in[2];
    const float* gq    = (const float*)d_in[3];
    const float* betaq = (const float*)d_in[4];
    const float* Wk    = (const float*)d_in[5];
    const float* bk    = (const float*)d_in[6];
    const float* gk    = (const float*)d_in[7];
    const float* betak = (const float*)d_in[8];
    const float* Wv    = (const float*)d_in[9];
    const float* bv    = (const float*)d_in[10];
    const float* gv    = (const float*)d_in[11];
    const float* betav = (const float*)d_in[12];

    cudaFuncSetAttribute(gemm_bf3<0>, cudaFuncAttributeMaxDynamicSharedMemorySize, SMEM_DYN);
    cudaFuncSetAttribute(gemm_bf3<1>, cudaFuncAttributeMaxDynamicSharedMemorySize, SMEM_DYN);
    cudaFuncSetAttribute(gemm_bf3<2>, cudaFuncAttributeMaxDynamicSharedMemorySize, SMEM_DYN);
    cudaFuncSetAttribute(gemm_bf3<3>, cudaFuncAttributeMaxDynamicSharedMemorySize, SMEM_DYN);

    float *Y, *Wsc, *sum, *sq;
    uint16_t *bf, *wth, *wtl;
    cudaGetSymbolAddress((void**)&Y,   g_Y);
    cudaGetSymbolAddress((void**)&Wsc, g_Wsc);
    cudaGetSymbolAddress((void**)&bf,  g_bf);
    cudaGetSymbolAddress((void**)&wth, g_wth);
    cudaGetSymbolAddress((void**)&wtl, g_wtl);
    cudaGetSymbolAddress((void**)&sum, g_sum);
    cudaGetSymbolAddress((void**)&sq,  g_sq);

    uint16_t* QH  = bf;
    uint16_t* QL  = bf + 1ULL * NMAT;
    uint16_t* KH  = bf + 2ULL * NMAT;
    uint16_t* KL  = bf + 3ULL * NMAT;
    uint16_t* VH  = bf + 4ULL * NMAT;
    uint16_t* VL  = bf + 5ULL * NMAT;
    uint16_t* WH  = bf + 6ULL * NMAT;
    uint16_t* WL  = bf + 7ULL * NMAT;
    uint16_t* X0H = bf + 8ULL * NMAT;
    uint16_t* X0L = bf + 9ULL * NMAT;
    uint16_t* X1H = bf + 10ULL * NMAT;
    uint16_t* X1L = bf + 11ULL * NMAT;

    float* Yq = Y;
    float* Yk = Y + 1ULL * NMAT;
    float* Yv = Y + 2ULL * NMAT;

    const dim3 gg(4, 4, BATCH);

    // weights -> bf16 hi/lo  (layout: [q=0,k=1,v=2][depth][512][512])
    cvt_split<<<3 * MAT / 4 / 256, 256>>>(Wq, wth + 0ULL * 3 * MAT, wtl + 0ULL * 3 * MAT);
    cvt_split<<<3 * MAT / 4 / 256, 256>>>(Wk, wth + 1ULL * 3 * MAT, wtl + 1ULL * 3 * MAT);
    cvt_split<<<3 * MAT / 4 / 256, 256>>>(Wv, wth + 2ULL * 3 * MAT, wtl + 2ULL * 3 * MAT);

    // xT[0] = transpose(P) split
    transpose_split<<<dim3(16, 16, BATCH), dim3(32, 8)>>>(P, X0H, X0L);

    for (int d = 0; d < 3; d++) {
        uint16_t* XiH = (d == 1) ? X1H : X0H;
        uint16_t* XiL = (d == 1) ? X1L : X0L;
        uint16_t* XoH = (d == 0) ? X1H : X0H;
        uint16_t* XoL = (d == 0) ? X1L : X0L;

        const uint16_t* wqh = wth + (0ULL * 3 + d) * MAT;
        const uint16_t* wql = wtl + (0ULL * 3 + d) * MAT;
        const uint16_t* wkh = wth + (1ULL * 3 + d) * MAT;
        const uint16_t* wkl = wtl + (1ULL * 3 + d) * MAT;
        const uint16_t* wvh = wth + (2ULL * 3 + d) * MAT;
        const uint16_t* wvl = wtl + (2ULL * 3 + d) * MAT;

        zero_stats<<<6, 256>>>();

        // Q[c][l] = Wq x xT (NT), row-stats
        gemm_bf3<1><<<gg, 256, SMEM_DYN>>>(wqh, wql, 0, XiH, XiL, MAT,
                                           Yq, nullptr, nullptr, bq + d * CH, sum, sq);
        gemm_bf3<1><<<gg, 256, SMEM_DYN>>>(wkh, wkl, 0, XiH, XiL, MAT,
                                           Yk, nullptr, nullptr, bk + d * CH, sum + CH, sq + CH);
        // VT[l][o] = xT x Wv (NT), col-stats
        gemm_bf3<2><<<gg, 256, SMEM_DYN>>>(XiH, XiL, MAT, wvh, wvl, 0,
                                           Yv, nullptr, nullptr, bv + d * CH, sum + 2 * CH, sq + 2 * CH);

        finalize_stats<<<6, 256>>>();

        bn_relu_row_split<<<NMAT / 4 / 256, 256>>>(Yq, gq + d * CH, betaq + d * CH, 0,      QH, QL);
        bn_relu_row_split<<<NMAT / 4 / 256, 256>>>(Yk, gk + d * CH, betak + d * CH, CH,     KH, KL);
        bn_relu_col_split<<<NMAT / 4 / 256, 256>>>(Yv, gv + d * CH, betav + d * CH, 2 * CH, VH, VL);

        // scores w[c][d'] = Q x K (NT over l)
        gemm_bf3<0><<<gg, 256, SMEM_DYN>>>(QH, QL, MAT, KH, KL, MAT,
                                           Wsc, nullptr, nullptr, nullptr, nullptr, nullptr);

        softmax_split<<<MAT / 256, 256>>>(Wsc, WH, WL);

        if (d < 2) {
            // xT_next[l][c] = VT x w (NT over d'), bf16 split out
            gemm_bf3<3><<<gg, 256, SMEM_DYN>>>(VH, VL, MAT, WH, WL, MAT,
                                               nullptr, XoH, XoL, nullptr, nullptr, nullptr);
        } else {
            // out[c][l] = w x VT (NT over d'), fp32 out
            gemm_bf3<0><<<gg, 256, SMEM_DYN>>>(WH, WL, MAT, VH, VL, MAT,
                                               (float*)d_out, nullptr, nullptr, nullptr, nullptr, nullptr);
        }
    }
}